// round 11
// baseline (speedup 1.0000x reference)
#include <cuda_runtime.h>
#include <cuda_bf16.h>
#include <cstdint>

#define BB 8
#define CC 128
#define HWN 4096
#define PC 384
#define NP 49280        // 3*CC*CC + CC
#define LAT 512
#define NSTEP 32
#define EPSV 1e-5f
#define NKS 24          // K = 384 = 24 * 16

// d_out layout (float32):
//  [0, 98304)               : clip(out[:, :3], -1, 1)
//  [98304, +33*EMB_SLICE)   : out_embs (33,8,128,64,64)
//  then                     : out_raw  (8,3,64,64)
#define OFF_EMBS (BB*3*HWN)
#define EMB_SLICE (BB*CC*HWN)
#define OFF_RAW (OFF_EMBS + 33*EMB_SLICE)

// B fragment pack: uint4 index = ((b*NKS+s)*512 + nf)*32 + q*8 + j
//   where pixel p = nf*8 + j, q = k-pair selector. {bh01, bh89, bl01, bl89}
__device__ uint4 g_ybp[(size_t)BB * NKS * 512 * 32];
// A fragment pack: per (b,s,f,lane): 16 halves = [hi frag 8][lo frag 8]. 1.6MB
__device__ __nv_bfloat16 g_wp[(size_t)BB * NKS * 8 * 512];
__device__ float g_params[BB * NP];

// ---------------------------------------------------------------------------
__device__ __forceinline__ void mma16816(float* d, uint4 a, uint32_t b0, uint32_t b1) {
    asm volatile(
        "mma.sync.aligned.m16n8k16.row.col.f32.bf16.bf16.f32 "
        "{%0,%1,%2,%3}, {%4,%5,%6,%7}, {%8,%9}, {%0,%1,%2,%3};"
        : "+f"(d[0]), "+f"(d[1]), "+f"(d[2]), "+f"(d[3])
        : "r"(a.x), "r"(a.y), "r"(a.z), "r"(a.w), "r"(b0), "r"(b1));
}

__device__ __forceinline__ uint32_t pk2(__nv_bfloat16 a, __nv_bfloat16 b) {
    __nv_bfloat162 p(a, b);   // a -> low 16 = first k of the pair
    return *(uint32_t*)&p;
}

// Build a B-fragment uint4 from 4 channel values of one pixel.
__device__ __forceinline__ uint4 fuse4(float v0, float v1, float v2, float v3) {
    __nv_bfloat16 h0 = __float2bfloat16(v0), h1 = __float2bfloat16(v1);
    __nv_bfloat16 h2 = __float2bfloat16(v2), h3 = __float2bfloat16(v3);
    __nv_bfloat16 l0 = __float2bfloat16(v0 - __bfloat162float(h0));
    __nv_bfloat16 l1 = __float2bfloat16(v1 - __bfloat162float(h1));
    __nv_bfloat16 l2 = __float2bfloat16(v2 - __bfloat162float(h2));
    __nv_bfloat16 l3 = __float2bfloat16(v3 - __bfloat162float(h3));
    uint4 o;
    o.x = pk2(h0, h1); o.y = pk2(h2, h3);
    o.z = pk2(l0, l1); o.w = pk2(l2, l3);
    return o;
}

__device__ __forceinline__ void sobel_at(const float* T, int ii, int jj,
                                         float& xc, float& gx, float& gy) {
    float a = (ii > 0 && jj > 0)   ? T[(ii - 1) * 64 + jj - 1] : 0.f;
    float n = (ii > 0)             ? T[(ii - 1) * 64 + jj]     : 0.f;
    float c = (ii > 0 && jj < 63)  ? T[(ii - 1) * 64 + jj + 1] : 0.f;
    float d = (jj > 0)             ? T[ii * 64 + jj - 1]       : 0.f;
    float e = (jj < 63)            ? T[ii * 64 + jj + 1]       : 0.f;
    float f = (ii < 63 && jj > 0)  ? T[(ii + 1) * 64 + jj - 1] : 0.f;
    float g = (ii < 63)            ? T[(ii + 1) * 64 + jj]     : 0.f;
    float h = (ii < 63 && jj < 63) ? T[(ii + 1) * 64 + jj + 1] : 0.f;
    xc = T[ii * 64 + jj];
    gx = ((c - a) + 2.f * (e - d) + (h - f)) * 0.125f;
    gy = ((f - a) + 2.f * (g - n) + (h - c)) * 0.125f;
}

// ---------------------------------------------------------------------------
// params[b,p] = lat[b] @ w_dyn[:,p] + b_dyn[p]; weights split hi/lo bf16 into
// the A fragment pack (one-time kernel).
// ---------------------------------------------------------------------------
__global__ void params_kernel(const float* __restrict__ lat,
                              const float* __restrict__ w_dyn,
                              const float* __restrict__ b_dyn) {
    __shared__ float slat[BB * LAT];
    int tid = threadIdx.x;
    for (int i = tid; i < BB * LAT; i += blockDim.x) slat[i] = lat[i];
    __syncthreads();
    int p = blockIdx.x * blockDim.x + tid;
    if (p >= NP) return;
    float acc[BB];
#pragma unroll
    for (int b = 0; b < BB; b++) acc[b] = 0.f;
    for (int k = 0; k < LAT; k++) {
        float w = w_dyn[k * NP + p];
#pragma unroll
        for (int b = 0; b < BB; b++) acc[b] = fmaf(slat[b * LAT + k], w, acc[b]);
    }
    float bd = b_dyn[p];
    bool isw = p < 3 * CC * CC;
    size_t foff = 0;
    if (isw) {
        int m = p / PC, k = p % PC;
        int s = k >> 4, kk = k & 15, f = m >> 4, r = m & 15;
        int lane = (r & 7) * 4 + ((kk & 7) >> 1);
        int reg = (r >> 3) + ((kk >> 3) << 1);
        foff = (size_t)((s * 8 + f) * 512) + lane * 16 + reg * 2 + (kk & 1);
    }
#pragma unroll
    for (int b = 0; b < BB; b++) {
        float v = acc[b] + bd;
        g_params[b * NP + p] = v;
        if (isw) {
            __nv_bfloat16 h = __float2bfloat16(v);
            __nv_bfloat16 l = __float2bfloat16(v - __bfloat162float(h));
            size_t base = (size_t)b * NKS * 8 * 512 + foff;
            g_wp[base] = h;
            g_wp[base + 8] = l;
        }
    }
}

__global__ void seed_kernel(float* __restrict__ out) {
    float* e0 = out + OFF_EMBS;
    for (int i = blockIdx.x * blockDim.x + threadIdx.x; i < EMB_SLICE;
         i += gridDim.x * blockDim.x) {
        int p = i & (HWN - 1);
        e0[i] = (p == (32 * 64 + 32)) ? 1.0f : 0.0f;
    }
}

// ---------------------------------------------------------------------------
// Perception + instance norm + fragment pack, fused.
// One block per (b, sgroup, q): channels {sg*16+2q, +1, +8, +9}, which form
// complete B-fragment uint4 quads for the x / gx / gy k-parts.
// ---------------------------------------------------------------------------
__global__ __launch_bounds__(256) void perc_kernel(const float* __restrict__ state) {
    extern __shared__ __align__(16) float tiles[];   // 4 * 4096 floats = 64KB
    __shared__ float red[24][8];
    __shared__ float tot[24];
    __shared__ float stats[24];  // [part*8 + c4*2] = mean, [..+1] = rsig
    int blk = blockIdx.x;
    int b = blk >> 5;
    int sg = (blk >> 2) & 7;
    int q = blk & 3;
    int tid = threadIdx.x;
    int c0 = sg * 16 + 2 * q;
    int chs[4] = {c0, c0 + 1, c0 + 8, c0 + 9};

#pragma unroll
    for (int c4 = 0; c4 < 4; c4++) {
        const float4* src = (const float4*)(state + (size_t)(b * CC + chs[c4]) * HWN);
        float4* dst = (float4*)(tiles + c4 * HWN);
#pragma unroll
        for (int i = 0; i < 4; i++) dst[tid + 256 * i] = src[tid + 256 * i];
    }
    __syncthreads();

    // -------- pass A: stats --------
    float s[24];
#pragma unroll
    for (int k = 0; k < 24; k++) s[k] = 0.f;
#pragma unroll 4
    for (int i = 0; i < 16; i++) {
        int p = i * 256 + tid;
        int ii = p >> 6, jj = p & 63;
#pragma unroll
        for (int c4 = 0; c4 < 4; c4++) {
            float xc, gx, gy;
            sobel_at(tiles + c4 * HWN, ii, jj, xc, gx, gy);
            s[c4 * 6 + 0] += xc; s[c4 * 6 + 1] += xc * xc;
            s[c4 * 6 + 2] += gx; s[c4 * 6 + 3] += gx * gx;
            s[c4 * 6 + 4] += gy; s[c4 * 6 + 5] += gy * gy;
        }
    }
#pragma unroll
    for (int o = 16; o > 0; o >>= 1)
#pragma unroll
        for (int k = 0; k < 24; k++) s[k] += __shfl_down_sync(0xffffffffu, s[k], o);
    int warp = tid >> 5, lane = tid & 31;
    if (lane == 0)
#pragma unroll
        for (int k = 0; k < 24; k++) red[k][warp] = s[k];
    __syncthreads();
    if (tid < 24) {
        float t = 0;
#pragma unroll
        for (int w2 = 0; w2 < 8; w2++) t += red[tid][w2];
        tot[tid] = t;
    }
    __syncthreads();
    if (tid < 12) {
        int c4 = tid & 3, part = tid >> 2;
        const float inv = 1.f / 4096.f;
        float mean = tot[c4 * 6 + part * 2] * inv;
        float var = tot[c4 * 6 + part * 2 + 1] * inv - mean * mean;
        stats[part * 8 + c4 * 2] = mean;
        stats[part * 8 + c4 * 2 + 1] = rsqrtf(fmaxf(var, 0.f) + EPSV);
    }
    __syncthreads();

    // -------- pass B: normalize + pack --------
    size_t base0 = ((size_t)(b * NKS + sg) * 512) * 32;          // x part
    size_t base1 = ((size_t)(b * NKS + 8 + sg) * 512) * 32;      // gx part
    size_t base2 = ((size_t)(b * NKS + 16 + sg) * 512) * 32;     // gy part
    float m0[4], r0[4], m1[4], r1[4], m2[4], r2[4];
#pragma unroll
    for (int c4 = 0; c4 < 4; c4++) {
        m0[c4] = stats[0 * 8 + c4 * 2]; r0[c4] = stats[0 * 8 + c4 * 2 + 1];
        m1[c4] = stats[1 * 8 + c4 * 2]; r1[c4] = stats[1 * 8 + c4 * 2 + 1];
        m2[c4] = stats[2 * 8 + c4 * 2]; r2[c4] = stats[2 * 8 + c4 * 2 + 1];
    }
#pragma unroll 2
    for (int i = 0; i < 16; i++) {
        int p = i * 256 + tid;
        int ii = p >> 6, jj = p & 63;
        float vx[4], vgx[4], vgy[4];
#pragma unroll
        for (int c4 = 0; c4 < 4; c4++) {
            float xc, gx, gy;
            sobel_at(tiles + c4 * HWN, ii, jj, xc, gx, gy);
            vx[c4]  = (xc - m0[c4]) * r0[c4];
            vgx[c4] = (gx - m1[c4]) * r1[c4];
            vgy[c4] = (gy - m2[c4]) * r2[c4];
        }
        size_t idx = (size_t)(p >> 3) * 32 + q * 8 + (p & 7);
        g_ybp[base0 + idx] = fuse4(vx[0], vx[1], vx[2], vx[3]);
        g_ybp[base1 + idx] = fuse4(vgx[0], vgx[1], vgx[2], vgx[3]);
        g_ybp[base2 + idx] = fuse4(vgy[0], vgy[1], vgy[2], vgy[3]);
    }
}

// ---------------------------------------------------------------------------
// HMMA GEMM: CTA = 128 out x 64 pix, 8 warps (4m x 2n), K=384 in 24 k16 steps.
// 3-term bf16 split, fp32 accum. Fragment packs loaded directly; B prefetched.
// ---------------------------------------------------------------------------
__global__ __launch_bounds__(256) void gemm_kernel(const float* __restrict__ lf_ptr,
                                                   const float* __restrict__ prev,
                                                   float* __restrict__ next) {
    int tid = threadIdx.x;
    int warp = tid >> 5, lane = tid & 31;
    int wm = warp & 3, wn = warp >> 2;
    int b = blockIdx.y, pt = blockIdx.x;

    float acc[2][4][4];
#pragma unroll
    for (int f = 0; f < 2; f++)
#pragma unroll
        for (int g = 0; g < 4; g++)
#pragma unroll
            for (int q = 0; q < 4; q++) acc[f][g][q] = 0.f;

    const uint4* WP = (const uint4*)g_wp;
    const uint4* YP = g_ybp;
    int nf0 = pt * 8 + wn * 4;
    // permuted fragment layout: element = q*8 + j, with q = lane&3, j = lane>>2
    size_t ybase = ((size_t)b * NKS * 512 + nf0) * 32 + (lane & 3) * 8 + (lane >> 2);
    size_t abase = ((size_t)b * NKS * 8 + wm * 2) * 64 + lane * 2;

    uint4 bv[4];
#pragma unroll
    for (int g = 0; g < 4; g++) bv[g] = __ldg(&YP[ybase + (size_t)g * 32]);

    for (int s2 = 0; s2 < NKS; s2++) {
        size_t fb = abase + (size_t)s2 * 512;
        uint4 ah0 = __ldg(&WP[fb]);
        uint4 al0 = __ldg(&WP[fb + 1]);
        uint4 ah1 = __ldg(&WP[fb + 64]);
        uint4 al1 = __ldg(&WP[fb + 65]);
        uint4 nb[4];
        if (s2 < NKS - 1) {
            size_t yb = ybase + (size_t)(s2 + 1) * 512 * 32;
#pragma unroll
            for (int g = 0; g < 4; g++) nb[g] = __ldg(&YP[yb + (size_t)g * 32]);
        }
#pragma unroll
        for (int g = 0; g < 4; g++) {
            mma16816(acc[0][g], ah0, bv[g].x, bv[g].y);
            mma16816(acc[1][g], ah1, bv[g].x, bv[g].y);
            mma16816(acc[0][g], al0, bv[g].x, bv[g].y);
            mma16816(acc[1][g], al1, bv[g].x, bv[g].y);
            mma16816(acc[0][g], ah0, bv[g].z, bv[g].w);
            mma16816(acc[1][g], ah1, bv[g].z, bv[g].w);
        }
        if (s2 < NKS - 1) {
#pragma unroll
            for (int g = 0; g < 4; g++) bv[g] = nb[g];
        }
    }

    float lf = fminf(fmaxf(__ldg(lf_ptr), 0.001f), 1000.f);
#pragma unroll
    for (int f = 0; f < 2; f++) {
        int r_lo = wm * 32 + f * 16 + (lane >> 2);
        int r_hi = r_lo + 8;
        float b_lo = __ldg(&g_params[b * NP + 3 * CC * CC + r_lo]);
        float b_hi = __ldg(&g_params[b * NP + 3 * CC * CC + r_hi]);
        size_t row_lo = (size_t)(b * CC + r_lo) * HWN;
        size_t row_hi = (size_t)(b * CC + r_hi) * HWN;
#pragma unroll
        for (int g = 0; g < 4; g++) {
            int p = pt * 64 + wn * 32 + g * 8 + (lane & 3) * 2;
            float2 pv0 = __ldg((const float2*)(prev + row_lo + p));
            float2 pv1 = __ldg((const float2*)(prev + row_hi + p));
            float2 o0, o1;
            o0.x = pv0.x + lf * (acc[f][g][0] + b_lo);
            o0.y = pv0.y + lf * (acc[f][g][1] + b_lo);
            o1.x = pv1.x + lf * (acc[f][g][2] + b_hi);
            o1.y = pv1.y + lf * (acc[f][g][3] + b_hi);
            *(float2*)(next + row_lo + p) = o0;
            *(float2*)(next + row_hi + p) = o1;
        }
    }
}

__global__ void final_kernel(float* __restrict__ out) {
    const float* st = out + OFF_EMBS + (size_t)NSTEP * EMB_SLICE;
    int n = BB * 3 * HWN;
    int i = blockIdx.x * blockDim.x + threadIdx.x;
    if (i >= n) return;
    int p = i & (HWN - 1);
    int bc = i >> 12;
    int b = bc / 3, c = bc % 3;
    float v = st[(b * CC + c) * HWN + p];
    out[i] = fminf(fmaxf(v, -1.f), 1.f);
    out[OFF_RAW + i] = v;
}

extern "C" void kernel_launch(void* const* d_in, const int* in_sizes, int n_in,
                              void* d_out, int out_size) {
    const float* lat   = (const float*)d_in[0];
    const float* leak  = (const float*)d_in[1];
    const float* w_dyn = (const float*)d_in[2];
    const float* b_dyn = (const float*)d_in[3];
    float* out = (float*)d_out;

    static bool attr_done = false;
    if (!attr_done) {
        cudaFuncSetAttribute(perc_kernel, cudaFuncAttributeMaxDynamicSharedMemorySize,
                             4 * HWN * sizeof(float));
        attr_done = true;
    }

    params_kernel<<<(NP + 127) / 128, 128>>>(lat, w_dyn, b_dyn);
    seed_kernel<<<2048, 256>>>(out);
    for (int s = 0; s < NSTEP; s++) {
        const float* prev = out + OFF_EMBS + (size_t)s * EMB_SLICE;
        float* next = out + OFF_EMBS + (size_t)(s + 1) * EMB_SLICE;
        perc_kernel<<<BB * 32, 256, 4 * HWN * sizeof(float)>>>(prev);
        gemm_kernel<<<dim3(64, BB), 256>>>(leak, prev, next);
    }
    final_kernel<<<(BB * 3 * HWN + 255) / 256, 256>>>(out);
}

// round 12
// speedup vs baseline: 1.0795x; 1.0795x over previous
#include <cuda_runtime.h>
#include <cuda_bf16.h>
#include <cstdint>

#define BB 8
#define CC 128
#define HWN 4096
#define PC 384
#define NP 49280        // 3*CC*CC + CC
#define LAT 512
#define NSTEP 32
#define EPSV 1e-5f
#define NKS 24          // K = 384 = 24 * 16

// d_out layout (float32):
//  [0, 98304)               : clip(out[:, :3], -1, 1)
//  [98304, +33*EMB_SLICE)   : out_embs (33,8,128,64,64)
//  then                     : out_raw  (8,3,64,64)
#define OFF_EMBS (BB*3*HWN)
#define EMB_SLICE (BB*CC*HWN)
#define OFF_RAW (OFF_EMBS + 33*EMB_SLICE)

// Linear Y: per (b, k, pix): u32 = (hi bf16 low16) | (lo bf16 high16). 50.3MB
__device__ uint32_t g_ylin[(size_t)BB * PC * HWN];
// A fragment pack: per (b,s,f): 32 lanes x 16 halves = [hi frag 8][lo frag 8]
__device__ __nv_bfloat16 g_wp[(size_t)BB * NKS * 8 * 512];
__device__ float g_params[BB * NP];

// ---------------------------------------------------------------------------
__device__ __forceinline__ void mma16816(float* d, uint4 a, uint32_t b0, uint32_t b1) {
    asm volatile(
        "mma.sync.aligned.m16n8k16.row.col.f32.bf16.bf16.f32 "
        "{%0,%1,%2,%3}, {%4,%5,%6,%7}, {%8,%9}, {%0,%1,%2,%3};"
        : "+f"(d[0]), "+f"(d[1]), "+f"(d[2]), "+f"(d[3])
        : "r"(a.x), "r"(a.y), "r"(a.z), "r"(a.w), "r"(b0), "r"(b1));
}

__device__ __forceinline__ uint32_t fuse_hilo(float v) {
    __nv_bfloat16 h = __float2bfloat16(v);
    __nv_bfloat16 l = __float2bfloat16(v - __bfloat162float(h));
    __nv_bfloat162 p(h, l);
    return *(uint32_t*)&p;   // low16 = hi, high16 = lo
}

// ---------------------------------------------------------------------------
// params[b,p] = lat[b] @ w_dyn[:,p] + b_dyn[p]; weights split hi/lo bf16 into
// the A fragment pack (one-time kernel).
// ---------------------------------------------------------------------------
__global__ void params_kernel(const float* __restrict__ lat,
                              const float* __restrict__ w_dyn,
                              const float* __restrict__ b_dyn) {
    __shared__ float slat[BB * LAT];
    int tid = threadIdx.x;
    for (int i = tid; i < BB * LAT; i += blockDim.x) slat[i] = lat[i];
    __syncthreads();
    int p = blockIdx.x * blockDim.x + tid;
    if (p >= NP) return;
    float acc[BB];
#pragma unroll
    for (int b = 0; b < BB; b++) acc[b] = 0.f;
    for (int k = 0; k < LAT; k++) {
        float w = w_dyn[k * NP + p];
#pragma unroll
        for (int b = 0; b < BB; b++) acc[b] = fmaf(slat[b * LAT + k], w, acc[b]);
    }
    float bd = b_dyn[p];
    bool isw = p < 3 * CC * CC;
    size_t foff = 0;
    if (isw) {
        int m = p / PC, k = p % PC;
        int s = k >> 4, kk = k & 15, f = m >> 4, r = m & 15;
        int lane = (r & 7) * 4 + ((kk & 7) >> 1);
        int reg = (r >> 3) + ((kk >> 3) << 1);
        foff = (size_t)((s * 8 + f) * 512) + lane * 16 + reg * 2 + (kk & 1);
    }
#pragma unroll
    for (int b = 0; b < BB; b++) {
        float v = acc[b] + bd;
        g_params[b * NP + p] = v;
        if (isw) {
            __nv_bfloat16 h = __float2bfloat16(v);
            __nv_bfloat16 l = __float2bfloat16(v - __bfloat162float(h));
            size_t base = (size_t)b * NKS * 8 * 512 + foff;
            g_wp[base] = h;
            g_wp[base + 8] = l;
        }
    }
}

__global__ void seed_kernel(float* __restrict__ out) {
    float* e0 = out + OFF_EMBS;
    for (int i = blockIdx.x * blockDim.x + threadIdx.x; i < EMB_SLICE;
         i += gridDim.x * blockDim.x) {
        int p = i & (HWN - 1);
        e0[i] = (p == (32 * 64 + 32)) ? 1.0f : 0.0f;
    }
}

// ---------------------------------------------------------------------------
// Perception + instance norm -> linear fused hi/lo u32 per pixel, coalesced.
// One block per (b, c); channel c feeds k-rows {c, 128+c, 256+c}.
// ---------------------------------------------------------------------------
__global__ __launch_bounds__(256) void perc_kernel(const float* __restrict__ state) {
    __shared__ __align__(16) float tile[HWN];
    __shared__ float red[6][8];
    __shared__ float tot[6];
    int bc = blockIdx.x;
    int b = bc >> 7, c = bc & 127;
    const float* xp = state + bc * HWN;
    int tid = threadIdx.x;

#pragma unroll
    for (int r = 0; r < 4; r++) {
        int f = tid + 256 * r;
        ((float4*)tile)[f] = ((const float4*)xp)[f];
    }
    __syncthreads();

    float xv[16], gxv[16], gyv[16];
    float s0 = 0, s1 = 0, s2 = 0, s3 = 0, s4 = 0, s5 = 0;
#pragma unroll
    for (int r = 0; r < 4; r++) {
        int f = tid + 256 * r;
        int p0 = f * 4;
        int i = p0 >> 6;
        int j0 = p0 & 63;
#pragma unroll
        for (int q = 0; q < 4; q++) {
            int j = j0 + q;
            float xm1m1 = (i > 0 && j > 0)   ? tile[(i - 1) * 64 + j - 1] : 0.f;
            float xm1c  = (i > 0)            ? tile[(i - 1) * 64 + j]     : 0.f;
            float xm1p1 = (i > 0 && j < 63)  ? tile[(i - 1) * 64 + j + 1] : 0.f;
            float x0m1  = (j > 0)            ? tile[i * 64 + j - 1]       : 0.f;
            float x0p1  = (j < 63)           ? tile[i * 64 + j + 1]       : 0.f;
            float xp1m1 = (i < 63 && j > 0)  ? tile[(i + 1) * 64 + j - 1] : 0.f;
            float xp1c  = (i < 63)           ? tile[(i + 1) * 64 + j]     : 0.f;
            float xp1p1 = (i < 63 && j < 63) ? tile[(i + 1) * 64 + j + 1] : 0.f;
            float xc = tile[i * 64 + j];
            float gx = ((xm1p1 - xm1m1) + 2.f * (x0p1 - x0m1) + (xp1p1 - xp1m1)) * 0.125f;
            float gy = ((xp1m1 - xm1m1) + 2.f * (xp1c - xm1c) + (xp1p1 - xm1p1)) * 0.125f;
            int idx = r * 4 + q;
            xv[idx] = xc; gxv[idx] = gx; gyv[idx] = gy;
            s0 += xc; s1 += xc * xc;
            s2 += gx; s3 += gx * gx;
            s4 += gy; s5 += gy * gy;
        }
    }
    float s[6] = {s0, s1, s2, s3, s4, s5};
#pragma unroll
    for (int o = 16; o > 0; o >>= 1)
#pragma unroll
        for (int q = 0; q < 6; q++) s[q] += __shfl_down_sync(0xffffffffu, s[q], o);
    int warp = tid >> 5, lane = tid & 31;
    if (lane == 0)
#pragma unroll
        for (int q = 0; q < 6; q++) red[q][warp] = s[q];
    __syncthreads();
    if (tid < 6) {
        float t = 0;
#pragma unroll
        for (int w2 = 0; w2 < 8; w2++) t += red[tid][w2];
        tot[tid] = t;
    }
    __syncthreads();
    const float inv = 1.f / 4096.f;
    float mx  = tot[0] * inv;
    float mgx = tot[2] * inv;
    float mgy = tot[4] * inv;
    float rx  = rsqrtf(fmaxf(tot[1] * inv - mx * mx, 0.f) + EPSV);
    float rgx = rsqrtf(fmaxf(tot[3] * inv - mgx * mgx, 0.f) + EPSV);
    float rgy = rsqrtf(fmaxf(tot[5] * inv - mgy * mgy, 0.f) + EPSV);

    uint32_t* lx  = g_ylin + (size_t)(b * PC + c) * HWN;
    uint32_t* lgx = g_ylin + (size_t)(b * PC + CC + c) * HWN;
    uint32_t* lgy = g_ylin + (size_t)(b * PC + 2 * CC + c) * HWN;

#pragma unroll
    for (int r = 0; r < 4; r++) {
        int f = tid + 256 * r;
        int p0 = f * 4;
        int base = r * 4;
        uint4 ox, ogx, ogy;
        ox.x = fuse_hilo((xv[base + 0] - mx) * rx);
        ox.y = fuse_hilo((xv[base + 1] - mx) * rx);
        ox.z = fuse_hilo((xv[base + 2] - mx) * rx);
        ox.w = fuse_hilo((xv[base + 3] - mx) * rx);
        ogx.x = fuse_hilo((gxv[base + 0] - mgx) * rgx);
        ogx.y = fuse_hilo((gxv[base + 1] - mgx) * rgx);
        ogx.z = fuse_hilo((gxv[base + 2] - mgx) * rgx);
        ogx.w = fuse_hilo((gxv[base + 3] - mgx) * rgx);
        ogy.x = fuse_hilo((gyv[base + 0] - mgy) * rgy);
        ogy.y = fuse_hilo((gyv[base + 1] - mgy) * rgy);
        ogy.z = fuse_hilo((gyv[base + 2] - mgy) * rgy);
        ogy.w = fuse_hilo((gyv[base + 3] - mgy) * rgy);
        *(uint4*)(lx + p0) = ox;
        *(uint4*)(lgx + p0) = ogx;
        *(uint4*)(lgy + p0) = ogy;
    }
}

// ---------------------------------------------------------------------------
// HMMA GEMM with inline fragment packing from linear Y.
// CTA = 128 out x 64 pix, 8 warps (4m x 2n), K=384 in 24 k16 steps.
// 3-term bf16 split, fp32 accum.
// ---------------------------------------------------------------------------
__global__ __launch_bounds__(256) void gemm_kernel(const float* __restrict__ lf_ptr,
                                                   const float* __restrict__ prev,
                                                   float* __restrict__ next) {
    int tid = threadIdx.x;
    int warp = tid >> 5, lane = tid & 31;
    int wm = warp & 3, wn = warp >> 2;
    int b = blockIdx.y, pt = blockIdx.x;

    float acc[2][4][4];
#pragma unroll
    for (int f = 0; f < 2; f++)
#pragma unroll
        for (int g = 0; g < 4; g++)
#pragma unroll
            for (int q = 0; q < 4; q++) acc[f][g][q] = 0.f;

    const uint4* WP = (const uint4*)g_wp;
    size_t abase = ((size_t)b * NKS * 8 + wm * 2) * 64 + lane * 2;

    // B source: linear Y at pixel p_in = pt*64 + wn*32 + g*8 + j, rows per q.
    int q = lane & 3, j = lane >> 2;
    int p_in = pt * 64 + wn * 32 + j;
    const uint32_t* Ybase = g_ylin + (size_t)b * PC * HWN + p_in;

    for (int s2 = 0; s2 < NKS; s2++) {
        size_t fb = abase + (size_t)s2 * 512;
        uint4 ah0 = __ldg(&WP[fb]);
        uint4 al0 = __ldg(&WP[fb + 1]);
        uint4 ah1 = __ldg(&WP[fb + 64]);
        uint4 al1 = __ldg(&WP[fb + 65]);

        const uint32_t* L = Ybase + (size_t)(s2 * 16 + 2 * q) * HWN;
        uint32_t u0[4], u1[4], u2[4], u3[4];
#pragma unroll
        for (int g = 0; g < 4; g++) {
            const uint32_t* Lp = L + g * 8;
            u0[g] = __ldg(Lp);
            u1[g] = __ldg(Lp + HWN);
            u2[g] = __ldg(Lp + 8 * HWN);
            u3[g] = __ldg(Lp + 9 * HWN);
        }
#pragma unroll
        for (int g = 0; g < 4; g++) {
            uint32_t bh0 = __byte_perm(u0[g], u1[g], 0x5410);
            uint32_t bh1 = __byte_perm(u2[g], u3[g], 0x5410);
            uint32_t bl0 = __byte_perm(u0[g], u1[g], 0x7632);
            uint32_t bl1 = __byte_perm(u2[g], u3[g], 0x7632);
            mma16816(acc[0][g], ah0, bh0, bh1);
            mma16816(acc[1][g], ah1, bh0, bh1);
            mma16816(acc[0][g], al0, bh0, bh1);
            mma16816(acc[1][g], al1, bh0, bh1);
            mma16816(acc[0][g], ah0, bl0, bl1);
            mma16816(acc[1][g], ah1, bl0, bl1);
        }
    }

    float lf = fminf(fmaxf(__ldg(lf_ptr), 0.001f), 1000.f);
#pragma unroll
    for (int f = 0; f < 2; f++) {
        int r_lo = wm * 32 + f * 16 + (lane >> 2);
        int r_hi = r_lo + 8;
        float b_lo = __ldg(&g_params[b * NP + 3 * CC * CC + r_lo]);
        float b_hi = __ldg(&g_params[b * NP + 3 * CC * CC + r_hi]);
        size_t row_lo = (size_t)(b * CC + r_lo) * HWN;
        size_t row_hi = (size_t)(b * CC + r_hi) * HWN;
#pragma unroll
        for (int g = 0; g < 4; g++) {
            int p = pt * 64 + wn * 32 + g * 8 + (lane & 3) * 2;
            float2 pv0 = __ldg((const float2*)(prev + row_lo + p));
            float2 pv1 = __ldg((const float2*)(prev + row_hi + p));
            float2 o0, o1;
            o0.x = pv0.x + lf * (acc[f][g][0] + b_lo);
            o0.y = pv0.y + lf * (acc[f][g][1] + b_lo);
            o1.x = pv1.x + lf * (acc[f][g][2] + b_hi);
            o1.y = pv1.y + lf * (acc[f][g][3] + b_hi);
            *(float2*)(next + row_lo + p) = o0;
            *(float2*)(next + row_hi + p) = o1;
        }
    }
}

__global__ void final_kernel(float* __restrict__ out) {
    const float* st = out + OFF_EMBS + (size_t)NSTEP * EMB_SLICE;
    int n = BB * 3 * HWN;
    int i = blockIdx.x * blockDim.x + threadIdx.x;
    if (i >= n) return;
    int p = i & (HWN - 1);
    int bc = i >> 12;
    int b = bc / 3, c = bc % 3;
    float v = st[(b * CC + c) * HWN + p];
    out[i] = fminf(fmaxf(v, -1.f), 1.f);
    out[OFF_RAW + i] = v;
}

extern "C" void kernel_launch(void* const* d_in, const int* in_sizes, int n_in,
                              void* d_out, int out_size) {
    const float* lat   = (const float*)d_in[0];
    const float* leak  = (const float*)d_in[1];
    const float* w_dyn = (const float*)d_in[2];
    const float* b_dyn = (const float*)d_in[3];
    float* out = (float*)d_out;

    params_kernel<<<(NP + 127) / 128, 128>>>(lat, w_dyn, b_dyn);
    seed_kernel<<<2048, 256>>>(out);
    for (int s = 0; s < NSTEP; s++) {
        const float* prev = out + OFF_EMBS + (size_t)s * EMB_SLICE;
        float* next = out + OFF_EMBS + (size_t)(s + 1) * EMB_SLICE;
        perc_kernel<<<BB * CC, 256>>>(prev);
        gemm_kernel<<<dim3(64, BB), 256>>>(leak, prev, next);
    }
    final_kernel<<<(BB * 3 * HWN + 255) / 256, 256>>>(out);
}

// round 15
// speedup vs baseline: 1.1346x; 1.0511x over previous
#include <cuda_runtime.h>
#include <cuda_bf16.h>
#include <cstdint>

#define BB 8
#define CC 128
#define HWN 4096
#define PC 384
#define NP 49280        // 3*CC*CC + CC
#define LAT 512
#define NSTEP 32
#define EPSV 1e-5f
#define NKS 24          // K = 384 = 24 * 16
#define BROW 68         // padded smem row stride (u32) -> conflict-free LDS

// d_out layout (float32):
//  [0, 98304)               : clip(out[:, :3], -1, 1)
//  [98304, +33*EMB_SLICE)   : out_embs (33,8,128,64,64)
//  then                     : out_raw  (8,3,64,64)
#define OFF_EMBS (BB*3*HWN)
#define EMB_SLICE (BB*CC*HWN)
#define OFF_RAW (OFF_EMBS + 33*EMB_SLICE)

// Linear Y: per (b, k, pix): u32 = (hi bf16 low16) | (lo bf16 high16). 50.3MB
__device__ uint32_t g_ylin[(size_t)BB * PC * HWN];
// A fragment pack: per (b,s,f): 32 lanes x 16 halves = [hi frag 8][lo frag 8]
__device__ __nv_bfloat16 g_wp[(size_t)BB * NKS * 8 * 512];
__device__ float g_params[BB * NP];

// ---------------------------------------------------------------------------
__device__ __forceinline__ void mma16816(float* d, uint4 a, uint32_t b0, uint32_t b1) {
    asm volatile(
        "mma.sync.aligned.m16n8k16.row.col.f32.bf16.bf16.f32 "
        "{%0,%1,%2,%3}, {%4,%5,%6,%7}, {%8,%9}, {%0,%1,%2,%3};"
        : "+f"(d[0]), "+f"(d[1]), "+f"(d[2]), "+f"(d[3])
        : "r"(a.x), "r"(a.y), "r"(a.z), "r"(a.w), "r"(b0), "r"(b1));
}

__device__ __forceinline__ uint32_t fuse_hilo(float v) {
    __nv_bfloat16 h = __float2bfloat16(v);
    __nv_bfloat16 l = __float2bfloat16(v - __bfloat162float(h));
    __nv_bfloat162 p(h, l);
    return *(uint32_t*)&p;   // low16 = hi, high16 = lo
}

__device__ __forceinline__ uint32_t smem_u32(const void* p) {
    uint32_t a;
    asm("{ .reg .u64 t; cvta.to.shared.u64 t, %1; cvt.u32.u64 %0, t; }" : "=r"(a) : "l"(p));
    return a;
}

__device__ __forceinline__ void cp16(uint32_t dst, const void* src) {
    asm volatile("cp.async.cg.shared.global [%0], [%1], 16;" :: "r"(dst), "l"(src));
}
__device__ __forceinline__ void cp_commit() {
    asm volatile("cp.async.commit_group;" ::: "memory");
}
template <int N>
__device__ __forceinline__ void cp_wait() {
    asm volatile("cp.async.wait_group %0;" :: "n"(N) : "memory");
}

// ---------------------------------------------------------------------------
// params[b,p] = lat[b] @ w_dyn[:,p] + b_dyn[p]; weights split hi/lo bf16 into
// the A fragment pack (one-time kernel).
// ---------------------------------------------------------------------------
__global__ void params_kernel(const float* __restrict__ lat,
                              const float* __restrict__ w_dyn,
                              const float* __restrict__ b_dyn) {
    __shared__ float slat[BB * LAT];
    int tid = threadIdx.x;
    for (int i = tid; i < BB * LAT; i += blockDim.x) slat[i] = lat[i];
    __syncthreads();
    int p = blockIdx.x * blockDim.x + tid;
    if (p >= NP) return;
    float acc[BB];
#pragma unroll
    for (int b = 0; b < BB; b++) acc[b] = 0.f;
    for (int k = 0; k < LAT; k++) {
        float w = w_dyn[k * NP + p];
#pragma unroll
        for (int b = 0; b < BB; b++) acc[b] = fmaf(slat[b * LAT + k], w, acc[b]);
    }
    float bd = b_dyn[p];
    bool isw = p < 3 * CC * CC;
    size_t foff = 0;
    if (isw) {
        int m = p / PC, k = p % PC;
        int s = k >> 4, kk = k & 15, f = m >> 4, r = m & 15;
        int lane = (r & 7) * 4 + ((kk & 7) >> 1);
        int reg = (r >> 3) + ((kk >> 3) << 1);
        foff = (size_t)((s * 8 + f) * 512) + lane * 16 + reg * 2 + (kk & 1);
    }
#pragma unroll
    for (int b = 0; b < BB; b++) {
        float v = acc[b] + bd;
        g_params[b * NP + p] = v;
        if (isw) {
            __nv_bfloat16 h = __float2bfloat16(v);
            __nv_bfloat16 l = __float2bfloat16(v - __bfloat162float(h));
            size_t base = (size_t)b * NKS * 8 * 512 + foff;
            g_wp[base] = h;
            g_wp[base + 8] = l;
        }
    }
}

__global__ void seed_kernel(float* __restrict__ out) {
    float* e0 = out + OFF_EMBS;
    for (int i = blockIdx.x * blockDim.x + threadIdx.x; i < EMB_SLICE;
         i += gridDim.x * blockDim.x) {
        int p = i & (HWN - 1);
        e0[i] = (p == (32 * 64 + 32)) ? 1.0f : 0.0f;
    }
}

// ---------------------------------------------------------------------------
// Perception + instance norm -> linear fused hi/lo u32 per pixel, coalesced.
// One block per (b, c); channel c feeds k-rows {c, 128+c, 256+c}.
// ---------------------------------------------------------------------------
__global__ __launch_bounds__(256) void perc_kernel(const float* __restrict__ state) {
    __shared__ __align__(16) float tile[HWN];
    __shared__ float red[6][8];
    __shared__ float tot[6];
    int bc = blockIdx.x;
    int b = bc >> 7, c = bc & 127;
    const float* xp = state + bc * HWN;
    int tid = threadIdx.x;

#pragma unroll
    for (int r = 0; r < 4; r++) {
        int f = tid + 256 * r;
        ((float4*)tile)[f] = ((const float4*)xp)[f];
    }
    __syncthreads();

    float xv[16], gxv[16], gyv[16];
    float s0 = 0, s1 = 0, s2 = 0, s3 = 0, s4 = 0, s5 = 0;
#pragma unroll
    for (int r = 0; r < 4; r++) {
        int f = tid + 256 * r;
        int p0 = f * 4;
        int i = p0 >> 6;
        int j0 = p0 & 63;
#pragma unroll
        for (int q = 0; q < 4; q++) {
            int j = j0 + q;
            float xm1m1 = (i > 0 && j > 0)   ? tile[(i - 1) * 64 + j - 1] : 0.f;
            float xm1c  = (i > 0)            ? tile[(i - 1) * 64 + j]     : 0.f;
            float xm1p1 = (i > 0 && j < 63)  ? tile[(i - 1) * 64 + j + 1] : 0.f;
            float x0m1  = (j > 0)            ? tile[i * 64 + j - 1]       : 0.f;
            float x0p1  = (j < 63)           ? tile[i * 64 + j + 1]       : 0.f;
            float xp1m1 = (i < 63 && j > 0)  ? tile[(i + 1) * 64 + j - 1] : 0.f;
            float xp1c  = (i < 63)           ? tile[(i + 1) * 64 + j]     : 0.f;
            float xp1p1 = (i < 63 && j < 63) ? tile[(i + 1) * 64 + j + 1] : 0.f;
            float xc = tile[i * 64 + j];
            float gx = ((xm1p1 - xm1m1) + 2.f * (x0p1 - x0m1) + (xp1p1 - xp1m1)) * 0.125f;
            float gy = ((xp1m1 - xm1m1) + 2.f * (xp1c - xm1c) + (xp1p1 - xm1p1)) * 0.125f;
            int idx = r * 4 + q;
            xv[idx] = xc; gxv[idx] = gx; gyv[idx] = gy;
            s0 += xc; s1 += xc * xc;
            s2 += gx; s3 += gx * gx;
            s4 += gy; s5 += gy * gy;
        }
    }
    float s[6] = {s0, s1, s2, s3, s4, s5};
#pragma unroll
    for (int o = 16; o > 0; o >>= 1)
#pragma unroll
        for (int q = 0; q < 6; q++) s[q] += __shfl_down_sync(0xffffffffu, s[q], o);
    int warp = tid >> 5, lane = tid & 31;
    if (lane == 0)
#pragma unroll
        for (int q = 0; q < 6; q++) red[q][warp] = s[q];
    __syncthreads();
    if (tid < 6) {
        float t = 0;
#pragma unroll
        for (int w2 = 0; w2 < 8; w2++) t += red[tid][w2];
        tot[tid] = t;
    }
    __syncthreads();
    const float inv = 1.f / 4096.f;
    float mx  = tot[0] * inv;
    float mgx = tot[2] * inv;
    float mgy = tot[4] * inv;
    float rx  = rsqrtf(fmaxf(tot[1] * inv - mx * mx, 0.f) + EPSV);
    float rgx = rsqrtf(fmaxf(tot[3] * inv - mgx * mgx, 0.f) + EPSV);
    float rgy = rsqrtf(fmaxf(tot[5] * inv - mgy * mgy, 0.f) + EPSV);

    uint32_t* lx  = g_ylin + (size_t)(b * PC + c) * HWN;
    uint32_t* lgx = g_ylin + (size_t)(b * PC + CC + c) * HWN;
    uint32_t* lgy = g_ylin + (size_t)(b * PC + 2 * CC + c) * HWN;

#pragma unroll
    for (int r = 0; r < 4; r++) {
        int f = tid + 256 * r;
        int p0 = f * 4;
        int base = r * 4;
        uint4 ox, ogx, ogy;
        ox.x = fuse_hilo((xv[base + 0] - mx) * rx);
        ox.y = fuse_hilo((xv[base + 1] - mx) * rx);
        ox.z = fuse_hilo((xv[base + 2] - mx) * rx);
        ox.w = fuse_hilo((xv[base + 3] - mx) * rx);
        ogx.x = fuse_hilo((gxv[base + 0] - mgx) * rgx);
        ogx.y = fuse_hilo((gxv[base + 1] - mgx) * rgx);
        ogx.z = fuse_hilo((gxv[base + 2] - mgx) * rgx);
        ogx.w = fuse_hilo((gxv[base + 3] - mgx) * rgx);
        ogy.x = fuse_hilo((gyv[base + 0] - mgy) * rgy);
        ogy.y = fuse_hilo((gyv[base + 1] - mgy) * rgy);
        ogy.z = fuse_hilo((gyv[base + 2] - mgy) * rgy);
        ogy.w = fuse_hilo((gyv[base + 3] - mgy) * rgy);
        *(uint4*)(lx + p0) = ox;
        *(uint4*)(lgx + p0) = ogx;
        *(uint4*)(lgy + p0) = ogy;
    }
}

// ---------------------------------------------------------------------------
// HMMA GEMM: cp.async 3-stage smem pipeline for B, register-prefetched A.
// Loop order: wait -> barrier -> issue (overwrite of stage consumed last
// iteration is now AFTER the barrier all warps cross post-consumption).
// CTA = 128 out x 64 pix, 8 warps (4m x 2n), K=384 in 24 k16 steps.
// ---------------------------------------------------------------------------
__global__ __launch_bounds__(256) void gemm_kernel(const float* __restrict__ lf_ptr,
                                                   const float* __restrict__ prev,
                                                   float* __restrict__ next) {
    __shared__ __align__(16) uint32_t Bs[3][16 * BROW];
    int tid = threadIdx.x;
    int warp = tid >> 5, lane = tid & 31;
    int wm = warp & 3, wn = warp >> 2;
    int b = blockIdx.y, pt = blockIdx.x;

    float acc[2][4][4];
#pragma unroll
    for (int f = 0; f < 2; f++)
#pragma unroll
        for (int g = 0; g < 4; g++)
#pragma unroll
            for (int q = 0; q < 4; q++) acc[f][g][q] = 0.f;

    const uint4* WP = (const uint4*)g_wp;
    size_t abase = ((size_t)b * NKS * 8 + wm * 2) * 64 + lane * 2;

    // cp.async staging geometry: thread t copies 16B at (row = t>>4, col4 = t&15)
    int crow = tid >> 4, ccol = (tid & 15) * 4;
    const uint32_t* Ysrc = g_ylin + (size_t)b * PC * HWN + pt * 64 + (size_t)crow * HWN + ccol;
    uint32_t dst_off[3];
#pragma unroll
    for (int st = 0; st < 3; st++)
        dst_off[st] = smem_u32(&Bs[st][crow * BROW + ccol]);

    // prologue: stages 0 and 1 in flight (one commit group each)
    cp16(dst_off[0], Ysrc);
    cp_commit();
    cp16(dst_off[1], Ysrc + (size_t)16 * HWN);
    cp_commit();

    uint4 ah0 = __ldg(&WP[abase]);
    uint4 al0 = __ldg(&WP[abase + 1]);
    uint4 ah1 = __ldg(&WP[abase + 64]);
    uint4 al1 = __ldg(&WP[abase + 65]);

    int q = lane & 3, j = lane >> 2;
    int px0 = wn * 32 + j;

    for (int s2 = 0; s2 < NKS; s2++) {
        // stage s2 resident (committed groups beyond it: at most stage s2+1)
        if (s2 < NKS - 1) cp_wait<1>();
        else cp_wait<0>();
        __syncthreads();
        // Now all warps have finished reading stage (s2-1)%3 == (s2+2)%3:
        // safe to overwrite it.
        if (s2 + 2 < NKS) {
            cp16(dst_off[(s2 + 2) % 3], Ysrc + (size_t)(s2 + 2) * 16 * HWN);
            cp_commit();
        }
        uint4 nh0, nl0, nh1, nl1;
        if (s2 + 1 < NKS) {
            size_t fb = abase + (size_t)(s2 + 1) * 512;
            nh0 = __ldg(&WP[fb]);
            nl0 = __ldg(&WP[fb + 1]);
            nh1 = __ldg(&WP[fb + 64]);
            nl1 = __ldg(&WP[fb + 65]);
        }

        const uint32_t* S = Bs[s2 % 3];
        const uint32_t* Sq0 = S + (2 * q) * BROW + px0;
        const uint32_t* Sq8 = S + (2 * q + 8) * BROW + px0;
#pragma unroll
        for (int g = 0; g < 4; g++) {
            uint32_t u0 = Sq0[g * 8];
            uint32_t u1 = Sq0[BROW + g * 8];
            uint32_t u2 = Sq8[g * 8];
            uint32_t u3 = Sq8[BROW + g * 8];
            uint32_t bh0 = __byte_perm(u0, u1, 0x5410);
            uint32_t bh1 = __byte_perm(u2, u3, 0x5410);
            uint32_t bl0 = __byte_perm(u0, u1, 0x7632);
            uint32_t bl1 = __byte_perm(u2, u3, 0x7632);
            mma16816(acc[0][g], ah0, bh0, bh1);
            mma16816(acc[1][g], ah1, bh0, bh1);
            mma16816(acc[0][g], al0, bh0, bh1);
            mma16816(acc[1][g], al1, bh0, bh1);
            mma16816(acc[0][g], ah0, bl0, bl1);
            mma16816(acc[1][g], ah1, bl0, bl1);
        }
        ah0 = nh0; al0 = nl0; ah1 = nh1; al1 = nl1;
    }

    float lf = fminf(fmaxf(__ldg(lf_ptr), 0.001f), 1000.f);
#pragma unroll
    for (int f = 0; f < 2; f++) {
        int r_lo = wm * 32 + f * 16 + (lane >> 2);
        int r_hi = r_lo + 8;
        float b_lo = __ldg(&g_params[b * NP + 3 * CC * CC + r_lo]);
        float b_hi = __ldg(&g_params[b * NP + 3 * CC * CC + r_hi]);
        size_t row_lo = (size_t)(b * CC + r_lo) * HWN;
        size_t row_hi = (size_t)(b * CC + r_hi) * HWN;
#pragma unroll
        for (int g = 0; g < 4; g++) {
            int p = pt * 64 + wn * 32 + g * 8 + (lane & 3) * 2;
            float2 pv0 = __ldg((const float2*)(prev + row_lo + p));
            float2 pv1 = __ldg((const float2*)(prev + row_hi + p));
            float2 o0, o1;
            o0.x = pv0.x + lf * (acc[f][g][0] + b_lo);
            o0.y = pv0.y + lf * (acc[f][g][1] + b_lo);
            o1.x = pv1.x + lf * (acc[f][g][2] + b_hi);
            o1.y = pv1.y + lf * (acc[f][g][3] + b_hi);
            *(float2*)(next + row_lo + p) = o0;
            *(float2*)(next + row_hi + p) = o1;
        }
    }
}

__global__ void final_kernel(float* __restrict__ out) {
    const float* st = out + OFF_EMBS + (size_t)NSTEP * EMB_SLICE;
    int n = BB * 3 * HWN;
    int i = blockIdx.x * blockDim.x + threadIdx.x;
    if (i >= n) return;
    int p = i & (HWN - 1);
    int bc = i >> 12;
    int b = bc / 3, c = bc % 3;
    float v = st[(b * CC + c) * HWN + p];
    out[i] = fminf(fmaxf(v, -1.f), 1.f);
    out[OFF_RAW + i] = v;
}

extern "C" void kernel_launch(void* const* d_in, const int* in_sizes, int n_in,
                              void* d_out, int out_size) {
    const float* lat   = (const float*)d_in[0];
    const float* leak  = (const float*)d_in[1];
    const float* w_dyn = (const float*)d_in[2];
    const float* b_dyn = (const float*)d_in[3];
    float* out = (float*)d_out;

    params_kernel<<<(NP + 127) / 128, 128>>>(lat, w_dyn, b_dyn);
    seed_kernel<<<2048, 256>>>(out);
    for (int s = 0; s < NSTEP; s++) {
        const float* prev = out + OFF_EMBS + (size_t)s * EMB_SLICE;
        float* next = out + OFF_EMBS + (size_t)(s + 1) * EMB_SLICE;
        perc_kernel<<<BB * CC, 256>>>(prev);
        gemm_kernel<<<dim3(64, BB), 256>>>(leak, prev, next);
    }
    final_kernel<<<(BB * 3 * HWN + 255) / 256, 256>>>(out);
}